// round 5
// baseline (speedup 1.0000x reference)
#include <cuda_runtime.h>
#include <math.h>

#define NB 4
#define NS 2048
#define ND 1024
#define NH 16
#define NDK 64
#define NM (NB*NS)

// Scratch (device globals: allocation-free rule)
__device__ float g_q[(size_t)NM*ND];
__device__ float g_k[(size_t)NM*ND];
__device__ float g_v[(size_t)NM*ND];
__device__ float g_o[(size_t)NM*ND];
__device__ float g_cos[NS*(NDK/2)];
__device__ float g_sin[NS*(NDK/2)];

// ---------------------------------------------------------------------------
// RoPE cos/sin table
// ---------------------------------------------------------------------------
__global__ void rope_table_kernel() {
    int idx = blockIdx.x * blockDim.x + threadIdx.x;
    if (idx >= NS * 32) return;
    int s = idx >> 5;
    int i = idx & 31;
    double freq = exp(-((double)(2 * i) / (double)NDK) * log(10000.0));
    double ang = (double)s * freq;
    g_cos[idx] = (float)cos(ang);
    g_sin[idx] = (float)sin(ang);
}

// ---------------------------------------------------------------------------
// tf32 helpers
// ---------------------------------------------------------------------------
__device__ __forceinline__ unsigned f2tf32(float x) {
    unsigned r;
    asm("cvt.rna.tf32.f32 %0, %1;" : "=r"(r) : "f"(x));
    return r;
}

__device__ __forceinline__ void mma_tf32(float* c, const unsigned* a, const unsigned* b) {
    asm volatile("mma.sync.aligned.m16n8k8.row.col.f32.tf32.tf32.f32 "
                 "{%0,%1,%2,%3}, {%4,%5,%6,%7}, {%8,%9}, {%0,%1,%2,%3};"
                 : "+f"(c[0]), "+f"(c[1]), "+f"(c[2]), "+f"(c[3])
                 : "r"(a[0]), "r"(a[1]), "r"(a[2]), "r"(a[3]),
                   "r"(b[0]), "r"(b[1]));
}

// ---------------------------------------------------------------------------
// Tensor-core NT GEMM v2: C[m,n] = sum_k A[m,k] * Wt[n,k].
// BM=BN=128, BK=16, double-buffered SMEM holding tf32 (converted at store),
// pair-permuted columns (slot 2t <- logical t, slot 2t+1 <- logical t+4)
// so each mma fragment pair is one LDS.64. 8 warps, warp tile 64x32.
// blockIdx.z selects one of up to 3 (W, C) pairs; z < nrope => fused RoPE.
// ---------------------------------------------------------------------------
#define GSTR 18

__global__ __launch_bounds__(256, 2) void gemm_tc2(
    const float* __restrict__ A,
    const float* __restrict__ Wa, const float* __restrict__ Wb, const float* __restrict__ Wc,
    float* __restrict__ Ca, float* __restrict__ Cb, float* __restrict__ Cc,
    int nrope)
{
    const float* Wt = (blockIdx.z == 0) ? Wa : (blockIdx.z == 1 ? Wb : Wc);
    float*       C  = (blockIdx.z == 0) ? Ca : (blockIdx.z == 1 ? Cb : Cc);
    const int rope  = (int)blockIdx.z < nrope;

    __shared__ unsigned As[2][128][GSTR];
    __shared__ unsigned Bs[2][128][GSTR];

    const int tid  = threadIdx.x;
    const int warp = tid >> 5;
    const int lane = tid & 31;
    const int wm   = warp >> 2;
    const int wn   = warp & 3;
    const int gid  = lane >> 2;
    const int tig  = lane & 3;
    const int bm   = blockIdx.y * 128;
    const int bn   = blockIdx.x * 128;

    const int lrow = tid >> 1;
    const int lgrp = (tid & 1) << 3;   // 0 or 8
    const float* Ap = A  + (size_t)(bm + lrow) * ND + lgrp;
    const float* Wp = Wt + (size_t)(bn + lrow) * ND + lgrp;

    float acc[4][4][4];
    #pragma unroll
    for (int mt = 0; mt < 4; mt++)
        #pragma unroll
        for (int nt = 0; nt < 4; nt++)
            #pragma unroll
            for (int c = 0; c < 4; c++) acc[mt][nt][c] = 0.0f;

    float4 ra0 = *(const float4*)(Ap);
    float4 ra1 = *(const float4*)(Ap + 4);
    float4 rb0 = *(const float4*)(Wp);
    float4 rb1 = *(const float4*)(Wp + 4);

    // pair-permuted store: slot 2t = logical col t, slot 2t+1 = logical col t+4
    {
        unsigned* as = &As[0][lrow][lgrp];
        *(uint2*)(as + 0) = make_uint2(f2tf32(ra0.x), f2tf32(ra1.x));
        *(uint2*)(as + 2) = make_uint2(f2tf32(ra0.y), f2tf32(ra1.y));
        *(uint2*)(as + 4) = make_uint2(f2tf32(ra0.z), f2tf32(ra1.z));
        *(uint2*)(as + 6) = make_uint2(f2tf32(ra0.w), f2tf32(ra1.w));
        unsigned* bs = &Bs[0][lrow][lgrp];
        *(uint2*)(bs + 0) = make_uint2(f2tf32(rb0.x), f2tf32(rb1.x));
        *(uint2*)(bs + 2) = make_uint2(f2tf32(rb0.y), f2tf32(rb1.y));
        *(uint2*)(bs + 4) = make_uint2(f2tf32(rb0.z), f2tf32(rb1.z));
        *(uint2*)(bs + 6) = make_uint2(f2tf32(rb0.w), f2tf32(rb1.w));
    }
    __syncthreads();

    for (int t = 0; t < 64; t++) {
        const int cur = t & 1;
        if (t < 63) {
            const float* ap = Ap + (t + 1) * 16;
            const float* wp = Wp + (t + 1) * 16;
            ra0 = *(const float4*)(ap);
            ra1 = *(const float4*)(ap + 4);
            rb0 = *(const float4*)(wp);
            rb1 = *(const float4*)(wp + 4);
        }

        const unsigned (*as)[GSTR] = As[cur];
        const unsigned (*bs)[GSTR] = Bs[cur];
        #pragma unroll
        for (int ks = 0; ks < 16; ks += 8) {
            unsigned af[4][4], bf[4][2];
            #pragma unroll
            for (int mt = 0; mt < 4; mt++) {
                int r = wm * 64 + mt * 16 + gid;
                uint2 a02 = *(const uint2*)&as[r    ][ks + 2 * tig];
                uint2 a13 = *(const uint2*)&as[r + 8][ks + 2 * tig];
                af[mt][0] = a02.x; af[mt][1] = a13.x;
                af[mt][2] = a02.y; af[mt][3] = a13.y;
            }
            #pragma unroll
            for (int nt = 0; nt < 4; nt++) {
                int n = wn * 32 + nt * 8 + gid;
                uint2 b01 = *(const uint2*)&bs[n][ks + 2 * tig];
                bf[nt][0] = b01.x; bf[nt][1] = b01.y;
            }
            #pragma unroll
            for (int mt = 0; mt < 4; mt++)
                #pragma unroll
                for (int nt = 0; nt < 4; nt++)
                    mma_tf32(acc[mt][nt], af[mt], bf[nt]);
        }

        if (t < 63) {
            unsigned* asn = &As[cur ^ 1][lrow][lgrp];
            *(uint2*)(asn + 0) = make_uint2(f2tf32(ra0.x), f2tf32(ra1.x));
            *(uint2*)(asn + 2) = make_uint2(f2tf32(ra0.y), f2tf32(ra1.y));
            *(uint2*)(asn + 4) = make_uint2(f2tf32(ra0.z), f2tf32(ra1.z));
            *(uint2*)(asn + 6) = make_uint2(f2tf32(ra0.w), f2tf32(ra1.w));
            unsigned* bsn = &Bs[cur ^ 1][lrow][lgrp];
            *(uint2*)(bsn + 0) = make_uint2(f2tf32(rb0.x), f2tf32(rb1.x));
            *(uint2*)(bsn + 2) = make_uint2(f2tf32(rb0.y), f2tf32(rb1.y));
            *(uint2*)(bsn + 4) = make_uint2(f2tf32(rb0.z), f2tf32(rb1.z));
            *(uint2*)(bsn + 6) = make_uint2(f2tf32(rb0.w), f2tf32(rb1.w));
        }
        __syncthreads();
    }

    #pragma unroll
    for (int mt = 0; mt < 4; mt++) {
        int m0 = bm + wm * 64 + mt * 16 + gid;
        #pragma unroll
        for (int nt = 0; nt < 4; nt++) {
            int n = bn + wn * 32 + nt * 8 + 2 * tig;
            float c0 = acc[mt][nt][0], c1 = acc[mt][nt][1];
            float c2 = acc[mt][nt][2], c3 = acc[mt][nt][3];
            if (rope) {
                int ip = (n & 63) >> 1;
                int s0 = m0 & (NS - 1);
                int s1 = (m0 + 8) & (NS - 1);
                float ca = g_cos[s0 * 32 + ip], sa = g_sin[s0 * 32 + ip];
                float cb = g_cos[s1 * 32 + ip], sb = g_sin[s1 * 32 + ip];
                float t0 = c0 * ca - c1 * sa;
                float t1 = c0 * sa + c1 * ca;
                float t2 = c2 * cb - c3 * sb;
                float t3 = c2 * sb + c3 * cb;
                c0 = t0; c1 = t1; c2 = t2; c3 = t3;
            }
            *(float2*)(C + (size_t)m0 * ND + n)       = make_float2(c0, c1);
            *(float2*)(C + (size_t)(m0 + 8) * ND + n) = make_float2(c2, c3);
        }
    }
}

// ---------------------------------------------------------------------------
// Tensor-core causal flash attention (tf32 mma), v2.
// grid = (S/128, H, B), 256 threads (8 warps x 16 q-rows), 64-key tiles.
// K/V tiles stored pair-permuted so mma B-fragments are single LDS.64:
//   Ks: [kv][d-slot]   stride 72 (conflict-free frag reads)
//   Vt: [d][kv-slot]   stride 74 (conflict-free frag reads)
//   Ps: [q][d or kv]   stride 68 (Q staging + P staging)
// ---------------------------------------------------------------------------
#define FBK 72
#define FBV 74
#define FBP 68
#define FA2_SMEM ((64 * FBK + 64 * FBV + 128 * FBP) * (int)sizeof(float))

__global__ __launch_bounds__(256, 2) void flash_tc_kernel() {
    extern __shared__ float sm[];
    unsigned* Ks = (unsigned*)sm;
    unsigned* Vt = (unsigned*)(sm + 64 * FBK);
    float*    Ps = sm + 64 * FBK + 64 * FBV;

    const int tid  = threadIdx.x;
    const int warp = tid >> 5;
    const int lane = tid & 31;
    const int gid  = lane >> 2;
    const int tig  = lane & 3;
    const int q0   = blockIdx.x * 128;
    const int h    = blockIdx.y;
    const int b    = blockIdx.z;
    const size_t base = (size_t)(b * NS) * ND + (size_t)h * NDK;

    // stage Q (pre-scaled by 1/sqrt(DK), tf32) into Ps
    for (int l = tid; l < 128 * 16; l += 256) {
        int r = l >> 4;
        int c = (l & 15) << 2;
        float4 v = *(const float4*)(g_q + base + (size_t)(q0 + r) * ND + c);
        unsigned* dst = (unsigned*)(Ps + r * FBP + c);
        dst[0] = f2tf32(v.x * 0.125f);
        dst[1] = f2tf32(v.y * 0.125f);
        dst[2] = f2tf32(v.z * 0.125f);
        dst[3] = f2tf32(v.w * 0.125f);
    }
    __syncthreads();

    unsigned qf[8][4];
    {
        const unsigned* P0 = (const unsigned*)(Ps + (warp * 16 + gid) * FBP);
        const unsigned* P1 = (const unsigned*)(Ps + (warp * 16 + gid + 8) * FBP);
        #pragma unroll
        for (int ks = 0; ks < 8; ks++) {
            qf[ks][0] = P0[ks * 8 + tig];
            qf[ks][1] = P1[ks * 8 + tig];
            qf[ks][2] = P0[ks * 8 + tig + 4];
            qf[ks][3] = P1[ks * 8 + tig + 4];
        }
    }
    __syncthreads();

    float o[8][4];
    #pragma unroll
    for (int nt = 0; nt < 8; nt++)
        #pragma unroll
        for (int c = 0; c < 4; c++) o[nt][c] = 0.0f;
    float m_a = -1e30f, m_b = -1e30f, l_a = 0.0f, l_b = 0.0f;
    const int row_a = q0 + warp * 16 + gid;
    const int row_b = row_a + 8;
    const int nk = 2 * blockIdx.x + 2;

    for (int kt = 0; kt < nk; kt++) {
        const int k0 = kt * 64;

        // load K/V tiles, tf32-converted, pair-permuted
        for (int l = tid; l < 64 * 16; l += 256) {
            int r = l >> 4;             // kv row
            int c = (l & 15) << 2;      // d col base (mult of 4)
            size_t gidx = base + (size_t)(k0 + r) * ND + c;
            float4 kk = *(const float4*)(g_k + gidx);
            float4 vv = *(const float4*)(g_v + gidx);
            // K: logical d col L -> slot (L&~7) + 2*(L&3) + ((L>>2)&1)
            int sb = (c & ~7) | ((c & 4) ? 1 : 0);
            unsigned* kr = Ks + r * FBK;
            kr[sb + 0] = f2tf32(kk.x);
            kr[sb + 2] = f2tf32(kk.y);
            kr[sb + 4] = f2tf32(kk.z);
            kr[sb + 6] = f2tf32(kk.w);
            // V transposed: logical kv row r -> permuted slot
            int kvslot = (r & ~7) | (2 * (r & 3) + ((r >> 2) & 1));
            Vt[(c + 0) * FBV + kvslot] = f2tf32(vv.x);
            Vt[(c + 1) * FBV + kvslot] = f2tf32(vv.y);
            Vt[(c + 2) * FBV + kvslot] = f2tf32(vv.z);
            Vt[(c + 3) * FBV + kvslot] = f2tf32(vv.w);
        }
        __syncthreads();

        if (k0 <= q0 + warp * 16 + 15) {   // warp has >=1 valid row in tile
            // S = Q K^T
            float s[8][4];
            #pragma unroll
            for (int nt = 0; nt < 8; nt++)
                #pragma unroll
                for (int c = 0; c < 4; c++) s[nt][c] = 0.0f;

            #pragma unroll
            for (int ks = 0; ks < 8; ks++) {
                #pragma unroll
                for (int nt = 0; nt < 8; nt++) {
                    uint2 bp = *(const uint2*)(Ks + (nt * 8 + gid) * FBK + ks * 8 + 2 * tig);
                    unsigned bfr[2] = { bp.x, bp.y };
                    mma_tf32(s[nt], qf[ks], bfr);
                }
            }

            // causal mask (only tiles touching the diagonal)
            if (k0 + 63 > q0 + warp * 16) {
                #pragma unroll
                for (int nt = 0; nt < 8; nt++) {
                    int kg = k0 + nt * 8 + 2 * tig;
                    if (kg     > row_a) s[nt][0] = -1e30f;
                    if (kg + 1 > row_a) s[nt][1] = -1e30f;
                    if (kg     > row_b) s[nt][2] = -1e30f;
                    if (kg + 1 > row_b) s[nt][3] = -1e30f;
                }
            }

            // online softmax
            float mx_a = -1e30f, mx_b = -1e30f;
            #pragma unroll
            for (int nt = 0; nt < 8; nt++) {
                mx_a = fmaxf(mx_a, fmaxf(s[nt][0], s[nt][1]));
                mx_b = fmaxf(mx_b, fmaxf(s[nt][2], s[nt][3]));
            }
            mx_a = fmaxf(mx_a, __shfl_xor_sync(0xffffffffu, mx_a, 1));
            mx_a = fmaxf(mx_a, __shfl_xor_sync(0xffffffffu, mx_a, 2));
            mx_b = fmaxf(mx_b, __shfl_xor_sync(0xffffffffu, mx_b, 1));
            mx_b = fmaxf(mx_b, __shfl_xor_sync(0xffffffffu, mx_b, 2));

            float mn_a = fmaxf(m_a, mx_a), mn_b = fmaxf(m_b, mx_b);
            float al_a = __expf(m_a - mn_a), al_b = __expf(m_b - mn_b);
            float rs_a = 0.0f, rs_b = 0.0f;
            #pragma unroll
            for (int nt = 0; nt < 8; nt++) {
                s[nt][0] = __expf(s[nt][0] - mn_a);
                s[nt][1] = __expf(s[nt][1] - mn_a);
                s[nt][2] = __expf(s[nt][2] - mn_b);
                s[nt][3] = __expf(s[nt][3] - mn_b);
                rs_a += s[nt][0] + s[nt][1];
                rs_b += s[nt][2] + s[nt][3];
            }
            rs_a += __shfl_xor_sync(0xffffffffu, rs_a, 1);
            rs_a += __shfl_xor_sync(0xffffffffu, rs_a, 2);
            rs_b += __shfl_xor_sync(0xffffffffu, rs_b, 1);
            rs_b += __shfl_xor_sync(0xffffffffu, rs_b, 2);

            l_a = l_a * al_a + rs_a;
            l_b = l_b * al_b + rs_b;
            m_a = mn_a;
            m_b = mn_b;

            #pragma unroll
            for (int nt = 0; nt < 8; nt++) {
                o[nt][0] *= al_a; o[nt][1] *= al_a;
                o[nt][2] *= al_b; o[nt][3] *= al_b;
            }

            // P -> SMEM (tf32), own-warp region only
            unsigned* Pa = (unsigned*)(Ps + (warp * 16 + gid) * FBP);
            unsigned* Pb = (unsigned*)(Ps + (warp * 16 + gid + 8) * FBP);
            #pragma unroll
            for (int nt = 0; nt < 8; nt++) {
                int c = nt * 8 + 2 * tig;
                Pa[c]     = f2tf32(s[nt][0]);
                Pa[c + 1] = f2tf32(s[nt][1]);
                Pb[c]     = f2tf32(s[nt][2]);
                Pb[c + 1] = f2tf32(s[nt][3]);
            }
            __syncwarp();

            // O += P V
            #pragma unroll
            for (int ks = 0; ks < 8; ks++) {
                unsigned af[4];
                af[0] = ((const unsigned*)Pa)[ks * 8 + tig];
                af[1] = ((const unsigned*)Pb)[ks * 8 + tig];
                af[2] = ((const unsigned*)Pa)[ks * 8 + tig + 4];
                af[3] = ((const unsigned*)Pb)[ks * 8 + tig + 4];
                #pragma unroll
                for (int nt = 0; nt < 8; nt++) {
                    uint2 vp = *(const uint2*)(Vt + (nt * 8 + gid) * FBV + ks * 8 + 2 * tig);
                    unsigned bfr[2] = { vp.x, vp.y };
                    mma_tf32(o[nt], af, bfr);
                }
            }
        }
        __syncthreads();
    }

    // normalize + write O
    float ia = 1.0f / l_a, ib = 1.0f / l_b;
    #pragma unroll
    for (int nt = 0; nt < 8; nt++) {
        int d = nt * 8 + 2 * tig;
        *(float2*)(g_o + base + (size_t)row_a * ND + d) =
            make_float2(o[nt][0] * ia, o[nt][1] * ia);
        *(float2*)(g_o + base + (size_t)row_b * ND + d) =
            make_float2(o[nt][2] * ib, o[nt][3] * ib);
    }
}

// ---------------------------------------------------------------------------
extern "C" void kernel_launch(void* const* d_in, const int* in_sizes, int n_in,
                              void* d_out, int out_size) {
    const float* x  = (const float*)d_in[0];
    // d_in[1] = mask (bool tril) -- causality is hardcoded
    const float* wq = (const float*)d_in[2];
    const float* wk = (const float*)d_in[3];
    const float* wv = (const float*)d_in[4];
    const float* wo = (const float*)d_in[5];
    float* out = (float*)d_out;

    void *pq, *pk, *pv, *po;
    cudaGetSymbolAddress(&pq, g_q);
    cudaGetSymbolAddress(&pk, g_k);
    cudaGetSymbolAddress(&pv, g_v);
    cudaGetSymbolAddress(&po, g_o);

    cudaFuncSetAttribute(flash_tc_kernel,
                         cudaFuncAttributeMaxDynamicSharedMemorySize, FA2_SMEM);

    rope_table_kernel<<<(NS * 32 + 255) / 256, 256>>>();

    // fused Q/K/V projections (z = 0,1,2; RoPE on z<2)
    gemm_tc2<<<dim3(ND / 128, NM / 128, 3), 256>>>(
        x, wq, wk, wv, (float*)pq, (float*)pk, (float*)pv, 2);

    flash_tc_kernel<<<dim3(NS / 128, NH, NB), 256, FA2_SMEM>>>();

    // output projection
    gemm_tc2<<<dim3(ND / 128, NM / 128, 1), 256>>>(
        (const float*)po, wo, wo, wo, out, out, out, 0);
}

// round 6
// speedup vs baseline: 1.3325x; 1.3325x over previous
#include <cuda_runtime.h>
#include <math.h>

#define NB 4
#define NS 2048
#define ND 1024
#define NH 16
#define NDK 64
#define NM (NB*NS)

// Scratch (device globals: allocation-free rule)
__device__ float g_q[(size_t)NM*ND];
__device__ float g_k[(size_t)NM*ND];
__device__ float g_v[(size_t)NM*ND];
__device__ float g_o[(size_t)NM*ND];
__device__ float g_cos[NS*(NDK/2)];
__device__ float g_sin[NS*(NDK/2)];

// ---------------------------------------------------------------------------
// RoPE cos/sin table
// ---------------------------------------------------------------------------
__global__ void rope_table_kernel() {
    int idx = blockIdx.x * blockDim.x + threadIdx.x;
    if (idx >= NS * 32) return;
    int s = idx >> 5;
    int i = idx & 31;
    double freq = exp(-((double)(2 * i) / (double)NDK) * log(10000.0));
    double ang = (double)s * freq;
    g_cos[idx] = (float)cos(ang);
    g_sin[idx] = (float)sin(ang);
}

// ---------------------------------------------------------------------------
// tf32 helpers
// ---------------------------------------------------------------------------
__device__ __forceinline__ unsigned f2tf32(float x) {
    unsigned r;
    asm("cvt.rna.tf32.f32 %0, %1;" : "=r"(r) : "f"(x));
    return r;
}

__device__ __forceinline__ void mma_tf32(float* c, const unsigned* a, const unsigned* b) {
    asm volatile("mma.sync.aligned.m16n8k8.row.col.f32.tf32.tf32.f32 "
                 "{%0,%1,%2,%3}, {%4,%5,%6,%7}, {%8,%9}, {%0,%1,%2,%3};"
                 : "+f"(c[0]), "+f"(c[1]), "+f"(c[2]), "+f"(c[3])
                 : "r"(a[0]), "r"(a[1]), "r"(a[2]), "r"(a[3]),
                   "r"(b[0]), "r"(b[1]));
}

// ---------------------------------------------------------------------------
// Tensor-core NT GEMM (tf32): C[m,n] = sum_k A[m,k] * Wt[n,k].
// BM=BN=128, BK=32. 8 warps; warp tile 64x32; 4x4 m16n8k8 tiles per warp.
// SMEM holds tf32 (converted once at store). Layout identical to proven R3.
// blockIdx.z selects (W, C) pair; z < nrope => fused interleaved RoPE.
// ---------------------------------------------------------------------------
__global__ __launch_bounds__(256) void gemm_tc(
    const float* __restrict__ A,
    const float* __restrict__ Wa, const float* __restrict__ Wb, const float* __restrict__ Wc,
    float* __restrict__ Ca, float* __restrict__ Cb, float* __restrict__ Cc,
    int nrope)
{
    const float* Wt = (blockIdx.z == 0) ? Wa : (blockIdx.z == 1 ? Wb : Wc);
    float*       C  = (blockIdx.z == 0) ? Ca : (blockIdx.z == 1 ? Cb : Cc);
    const int rope  = (int)blockIdx.z < nrope;

    __shared__ unsigned As[128][36];
    __shared__ unsigned Bs[128][36];

    const int tid  = threadIdx.x;
    const int warp = tid >> 5;
    const int lane = tid & 31;
    const int wm   = warp >> 2;
    const int wn   = warp & 3;
    const int gid  = lane >> 2;
    const int tig  = lane & 3;
    const int bm   = blockIdx.y * 128;
    const int bn   = blockIdx.x * 128;

    float acc[4][4][4];
    #pragma unroll
    for (int mt = 0; mt < 4; mt++)
        #pragma unroll
        for (int nt = 0; nt < 4; nt++)
            #pragma unroll
            for (int c = 0; c < 4; c++) acc[mt][nt][c] = 0.0f;

    for (int k0 = 0; k0 < ND; k0 += 32) {
        #pragma unroll
        for (int i = 0; i < 4; i++) {
            int idx = i * 256 + tid;
            int r = idx >> 3;
            int c = (idx & 7) << 2;
            float4 a4 = *(const float4*)(A  + (size_t)(bm + r) * ND + k0 + c);
            float4 b4 = *(const float4*)(Wt + (size_t)(bn + r) * ND + k0 + c);
            *(uint4*)(&As[r][c]) = make_uint4(f2tf32(a4.x), f2tf32(a4.y),
                                              f2tf32(a4.z), f2tf32(a4.w));
            *(uint4*)(&Bs[r][c]) = make_uint4(f2tf32(b4.x), f2tf32(b4.y),
                                              f2tf32(b4.z), f2tf32(b4.w));
        }
        __syncthreads();

        #pragma unroll
        for (int ks = 0; ks < 32; ks += 8) {
            unsigned af[4][4], bf[4][2];
            #pragma unroll
            for (int mt = 0; mt < 4; mt++) {
                int r = wm * 64 + mt * 16 + gid;
                af[mt][0] = As[r    ][ks + tig];
                af[mt][1] = As[r + 8][ks + tig];
                af[mt][2] = As[r    ][ks + tig + 4];
                af[mt][3] = As[r + 8][ks + tig + 4];
            }
            #pragma unroll
            for (int nt = 0; nt < 4; nt++) {
                int n = wn * 32 + nt * 8 + gid;
                bf[nt][0] = Bs[n][ks + tig];
                bf[nt][1] = Bs[n][ks + tig + 4];
            }
            #pragma unroll
            for (int mt = 0; mt < 4; mt++)
                #pragma unroll
                for (int nt = 0; nt < 4; nt++)
                    mma_tf32(acc[mt][nt], af[mt], bf[nt]);
        }
        __syncthreads();
    }

    #pragma unroll
    for (int mt = 0; mt < 4; mt++) {
        int m0 = bm + wm * 64 + mt * 16 + gid;
        #pragma unroll
        for (int nt = 0; nt < 4; nt++) {
            int n = bn + wn * 32 + nt * 8 + 2 * tig;
            float c0 = acc[mt][nt][0], c1 = acc[mt][nt][1];
            float c2 = acc[mt][nt][2], c3 = acc[mt][nt][3];
            if (rope) {
                int ip = (n & 63) >> 1;
                int s0 = m0 & (NS - 1);
                int s1 = (m0 + 8) & (NS - 1);
                float ca = g_cos[s0 * 32 + ip], sa = g_sin[s0 * 32 + ip];
                float cb = g_cos[s1 * 32 + ip], sb = g_sin[s1 * 32 + ip];
                float t0 = c0 * ca - c1 * sa;
                float t1 = c0 * sa + c1 * ca;
                float t2 = c2 * cb - c3 * sb;
                float t3 = c2 * sb + c3 * cb;
                c0 = t0; c1 = t1; c2 = t2; c3 = t3;
            }
            *(float2*)(C + (size_t)m0 * ND + n)       = make_float2(c0, c1);
            *(float2*)(C + (size_t)(m0 + 8) * ND + n) = make_float2(c2, c3);
        }
    }
}

// ---------------------------------------------------------------------------
// Tensor-core causal flash attention (tf32 mma)  [proven R3 version].
// grid = (S/128, H, B), 256 threads (8 warps x 16 q-rows), 64-key tiles.
// ---------------------------------------------------------------------------
#define FB 68
#define FA2_SMEM ((64 + 64 + 128) * FB * (int)sizeof(float))

__global__ __launch_bounds__(256, 2) void flash_tc_kernel() {
    extern __shared__ float sm[];
    float* Ks = sm;
    float* Vt = sm + 64 * FB;
    float* Ps = sm + 128 * FB;

    const int tid  = threadIdx.x;
    const int warp = tid >> 5;
    const int lane = tid & 31;
    const int gid  = lane >> 2;
    const int tig  = lane & 3;
    const int q0   = blockIdx.x * 128;
    const int h    = blockIdx.y;
    const int b    = blockIdx.z;
    const size_t base = (size_t)(b * NS) * ND + (size_t)h * NDK;

    // stage Q (pre-scaled by 1/sqrt(DK), tf32) into Ps
    for (int l = tid; l < 128 * 16; l += 256) {
        int r = l >> 4;
        int c = (l & 15) << 2;
        float4 v = *(const float4*)(g_q + base + (size_t)(q0 + r) * ND + c);
        unsigned* dst = (unsigned*)(Ps + r * FB + c);
        dst[0] = f2tf32(v.x * 0.125f);
        dst[1] = f2tf32(v.y * 0.125f);
        dst[2] = f2tf32(v.z * 0.125f);
        dst[3] = f2tf32(v.w * 0.125f);
    }
    __syncthreads();

    unsigned qf[8][4];
    {
        const unsigned* P0 = (const unsigned*)(Ps + (warp * 16 + gid) * FB);
        const unsigned* P1 = (const unsigned*)(Ps + (warp * 16 + gid + 8) * FB);
        #pragma unroll
        for (int ks = 0; ks < 8; ks++) {
            qf[ks][0] = P0[ks * 8 + tig];
            qf[ks][1] = P1[ks * 8 + tig];
            qf[ks][2] = P0[ks * 8 + tig + 4];
            qf[ks][3] = P1[ks * 8 + tig + 4];
        }
    }
    __syncthreads();

    float o[8][4];
    #pragma unroll
    for (int nt = 0; nt < 8; nt++)
        #pragma unroll
        for (int c = 0; c < 4; c++) o[nt][c] = 0.0f;
    float m_a = -1e30f, m_b = -1e30f, l_a = 0.0f, l_b = 0.0f;
    const int row_a = q0 + warp * 16 + gid;
    const int row_b = row_a + 8;
    const int nk = 2 * blockIdx.x + 2;

    for (int kt = 0; kt < nk; kt++) {
        const int k0 = kt * 64;

        // load K tile [kv][d] and V tile transposed [d][kv], tf32-converted
        for (int l = tid; l < 64 * 16; l += 256) {
            int r = l >> 4;
            int c = (l & 15) << 2;
            size_t gidx = base + (size_t)(k0 + r) * ND + c;
            float4 kk = *(const float4*)(g_k + gidx);
            float4 vv = *(const float4*)(g_v + gidx);
            unsigned* kd = (unsigned*)(Ks + r * FB + c);
            kd[0] = f2tf32(kk.x);
            kd[1] = f2tf32(kk.y);
            kd[2] = f2tf32(kk.z);
            kd[3] = f2tf32(kk.w);
            ((unsigned*)Vt)[(c + 0) * FB + r] = f2tf32(vv.x);
            ((unsigned*)Vt)[(c + 1) * FB + r] = f2tf32(vv.y);
            ((unsigned*)Vt)[(c + 2) * FB + r] = f2tf32(vv.z);
            ((unsigned*)Vt)[(c + 3) * FB + r] = f2tf32(vv.w);
        }
        __syncthreads();

        if (k0 <= q0 + warp * 16 + 15) {   // warp has >=1 valid row in tile
            // S = Q K^T
            float s[8][4];
            #pragma unroll
            for (int nt = 0; nt < 8; nt++)
                #pragma unroll
                for (int c = 0; c < 4; c++) s[nt][c] = 0.0f;

            #pragma unroll
            for (int ks = 0; ks < 8; ks++) {
                #pragma unroll
                for (int nt = 0; nt < 8; nt++) {
                    const unsigned* Kp = (const unsigned*)(Ks + (nt * 8 + gid) * FB + ks * 8);
                    unsigned bfr[2] = { Kp[tig], Kp[tig + 4] };
                    mma_tf32(s[nt], qf[ks], bfr);
                }
            }

            // causal mask (only tiles touching the diagonal)
            if (k0 + 63 > q0 + warp * 16) {
                #pragma unroll
                for (int nt = 0; nt < 8; nt++) {
                    int kg = k0 + nt * 8 + 2 * tig;
                    if (kg     > row_a) s[nt][0] = -1e30f;
                    if (kg + 1 > row_a) s[nt][1] = -1e30f;
                    if (kg     > row_b) s[nt][2] = -1e30f;
                    if (kg + 1 > row_b) s[nt][3] = -1e30f;
                }
            }

            // online softmax
            float mx_a = -1e30f, mx_b = -1e30f;
            #pragma unroll
            for (int nt = 0; nt < 8; nt++) {
                mx_a = fmaxf(mx_a, fmaxf(s[nt][0], s[nt][1]));
                mx_b = fmaxf(mx_b, fmaxf(s[nt][2], s[nt][3]));
            }
            mx_a = fmaxf(mx_a, __shfl_xor_sync(0xffffffffu, mx_a, 1));
            mx_a = fmaxf(mx_a, __shfl_xor_sync(0xffffffffu, mx_a, 2));
            mx_b = fmaxf(mx_b, __shfl_xor_sync(0xffffffffu, mx_b, 1));
            mx_b = fmaxf(mx_b, __shfl_xor_sync(0xffffffffu, mx_b, 2));

            float mn_a = fmaxf(m_a, mx_a), mn_b = fmaxf(m_b, mx_b);
            float al_a = __expf(m_a - mn_a), al_b = __expf(m_b - mn_b);
            float rs_a = 0.0f, rs_b = 0.0f;
            #pragma unroll
            for (int nt = 0; nt < 8; nt++) {
                s[nt][0] = __expf(s[nt][0] - mn_a);
                s[nt][1] = __expf(s[nt][1] - mn_a);
                s[nt][2] = __expf(s[nt][2] - mn_b);
                s[nt][3] = __expf(s[nt][3] - mn_b);
                rs_a += s[nt][0] + s[nt][1];
                rs_b += s[nt][2] + s[nt][3];
            }
            rs_a += __shfl_xor_sync(0xffffffffu, rs_a, 1);
            rs_a += __shfl_xor_sync(0xffffffffu, rs_a, 2);
            rs_b += __shfl_xor_sync(0xffffffffu, rs_b, 1);
            rs_b += __shfl_xor_sync(0xffffffffu, rs_b, 2);

            l_a = l_a * al_a + rs_a;
            l_b = l_b * al_b + rs_b;
            m_a = mn_a;
            m_b = mn_b;

            #pragma unroll
            for (int nt = 0; nt < 8; nt++) {
                o[nt][0] *= al_a; o[nt][1] *= al_a;
                o[nt][2] *= al_b; o[nt][3] *= al_b;
            }

            // P -> SMEM (tf32), own-warp region only
            unsigned* Pa = (unsigned*)(Ps + (warp * 16 + gid) * FB);
            unsigned* Pb = (unsigned*)(Ps + (warp * 16 + gid + 8) * FB);
            #pragma unroll
            for (int nt = 0; nt < 8; nt++) {
                int c = nt * 8 + 2 * tig;
                Pa[c]     = f2tf32(s[nt][0]);
                Pa[c + 1] = f2tf32(s[nt][1]);
                Pb[c]     = f2tf32(s[nt][2]);
                Pb[c + 1] = f2tf32(s[nt][3]);
            }
            __syncwarp();

            // O += P V
            #pragma unroll
            for (int ks = 0; ks < 8; ks++) {
                unsigned af[4];
                af[0] = ((const unsigned*)Pa)[ks * 8 + tig];
                af[1] = ((const unsigned*)Pb)[ks * 8 + tig];
                af[2] = ((const unsigned*)Pa)[ks * 8 + tig + 4];
                af[3] = ((const unsigned*)Pb)[ks * 8 + tig + 4];
                #pragma unroll
                for (int nt = 0; nt < 8; nt++) {
                    const unsigned* Vp = (const unsigned*)(Vt + (nt * 8 + gid) * FB + ks * 8);
                    unsigned bfr[2] = { Vp[tig], Vp[tig + 4] };
                    mma_tf32(o[nt], af, bfr);
                }
            }
        }
        __syncthreads();
    }

    // normalize + write O
    float ia = 1.0f / l_a, ib = 1.0f / l_b;
    #pragma unroll
    for (int nt = 0; nt < 8; nt++) {
        int d = nt * 8 + 2 * tig;
        *(float2*)(g_o + base + (size_t)row_a * ND + d) =
            make_float2(o[nt][0] * ia, o[nt][1] * ia);
        *(float2*)(g_o + base + (size_t)row_b * ND + d) =
            make_float2(o[nt][2] * ib, o[nt][3] * ib);
    }
}

// ---------------------------------------------------------------------------
extern "C" void kernel_launch(void* const* d_in, const int* in_sizes, int n_in,
                              void* d_out, int out_size) {
    const float* x  = (const float*)d_in[0];
    // d_in[1] = mask (bool tril) -- causality is hardcoded
    const float* wq = (const float*)d_in[2];
    const float* wk = (const float*)d_in[3];
    const float* wv = (const float*)d_in[4];
    const float* wo = (const float*)d_in[5];
    float* out = (float*)d_out;

    void *pq, *pk, *pv, *po;
    cudaGetSymbolAddress(&pq, g_q);
    cudaGetSymbolAddress(&pk, g_k);
    cudaGetSymbolAddress(&pv, g_v);
    cudaGetSymbolAddress(&po, g_o);

    cudaFuncSetAttribute(flash_tc_kernel,
                         cudaFuncAttributeMaxDynamicSharedMemorySize, FA2_SMEM);

    rope_table_kernel<<<(NS * 32 + 255) / 256, 256>>>();

    // fused Q/K/V projections (z = 0,1,2; RoPE on z<2)
    gemm_tc<<<dim3(ND / 128, NM / 128, 3), 256>>>(
        x, wq, wk, wv, (float*)pq, (float*)pk, (float*)pv, 2);

    flash_tc_kernel<<<dim3(NS / 128, NH, NB), 256, FA2_SMEM>>>();

    // output projection
    gemm_tc<<<dim3(ND / 128, NM / 128, 1), 256>>>(
        (const float*)po, wo, wo, wo, out, out, out, 0);
}